// round 7
// baseline (speedup 1.0000x reference)
#include <cuda_runtime.h>
#include <cstdint>

// Max pool 2x2 stride 2, NCHW (32,128,224,224) fp32 -> (32,128,112,112)
// HBM-bound streaming: 822MB read + 206MB write (mandatory, zero reuse).
//
// R7: R4 read shape (2 quads/thread, 256 threads, die-after-work, MLP_p1=8)
// + write side via TMA bulk store: block's 512 output quads = one contiguous
// 8KB region -> stage in smem, single cp.async.bulk per block. Removes all
// STG traffic from the LSU path and batches DRAM writes into 8KB bursts.

#define IW   224
#define IH   224
#define OW   112
#define OH   112
#define OW4  28                       // float4 quads per output row
#define NC   (32 * 128)
#define TOTAL_QUADS (NC * OH * OW4)   // 12,845,056 = 512 * 25088

__device__ __forceinline__ void decode(int p, const float* __restrict__ in,
                                       const float4** r0, const float4** r1) {
    const int ow4 = p % OW4;
    const int t1  = p / OW4;
    const int oh  = t1 % OH;
    const int nc  = t1 / OH;
    const long long base = (long long)nc * (IH * IW) + (long long)(2 * oh) * IW + 8 * ow4;
    *r0 = reinterpret_cast<const float4*>(in + base);
    *r1 = reinterpret_cast<const float4*>(in + base + IW);
}

__device__ __forceinline__ float4 fmax4(float4 t0, float4 t1, float4 u0, float4 u1) {
    float4 r;
    r.x = fmaxf(fmaxf(t0.x, t0.y), fmaxf(u0.x, u0.y));
    r.y = fmaxf(fmaxf(t0.z, t0.w), fmaxf(u0.z, u0.w));
    r.z = fmaxf(fmaxf(t1.x, t1.y), fmaxf(u1.x, u1.y));
    r.w = fmaxf(fmaxf(t1.z, t1.w), fmaxf(u1.z, u1.w));
    return r;
}

__global__ __launch_bounds__(256, 8)
void pool2d_kernel(const float* __restrict__ in, float4* __restrict__ out) {
    __shared__ __align__(128) float4 sbuf[512];   // 8KB staging

    const int pA = blockIdx.x * 512 + threadIdx.x;
    const int pB = pA + 256;

    const float4 *a_r0, *a_r1, *b_r0, *b_r1;
    decode(pA, in, &a_r0, &a_r1);
    decode(pB, in, &b_r0, &b_r1);

    // 8 independent loads, front-batched
    const float4 a00 = __ldcs(a_r0);  const float4 a01 = __ldcs(a_r0 + 1);
    const float4 a10 = __ldcs(a_r1);  const float4 a11 = __ldcs(a_r1 + 1);
    const float4 b00 = __ldcs(b_r0);  const float4 b01 = __ldcs(b_r0 + 1);
    const float4 b10 = __ldcs(b_r1);  const float4 b11 = __ldcs(b_r1 + 1);

    sbuf[threadIdx.x]       = fmax4(a00, a01, a10, a11);
    sbuf[threadIdx.x + 256] = fmax4(b00, b01, b10, b11);

    __syncthreads();

    if (threadIdx.x == 0) {
        // make smem writes visible to the async proxy
        asm volatile("fence.proxy.async.shared::cta;" ::: "memory");
        uint32_t saddr;
        asm("{ .reg .u64 t; cvta.to.shared.u64 t, %1; cvt.u32.u64 %0, t; }"
            : "=r"(saddr) : "l"(sbuf));
        const float4* dst = out + (size_t)blockIdx.x * 512;
        asm volatile(
            "cp.async.bulk.global.shared::cta.bulk_group [%0], [%1], %2;"
            :: "l"(dst), "r"(saddr), "n"(8192) : "memory");
        asm volatile("cp.async.bulk.commit_group;" ::: "memory");
        asm volatile("cp.async.bulk.wait_group 0;" ::: "memory");
    }
}

extern "C" void kernel_launch(void* const* d_in, const int* in_sizes, int n_in,
                              void* d_out, int out_size) {
    const float* x = (const float*)d_in[0];
    float4* out = (float4*)d_out;

    const int blocks  = TOTAL_QUADS / 512;   // 25088, no tail
    const int threads = 256;

    pool2d_kernel<<<blocks, threads>>>(x, out);
}

// round 8
// speedup vs baseline: 1.1501x; 1.1501x over previous
#include <cuda_runtime.h>

// Max pool 2x2 stride 2, NCHW (32,128,224,224) fp32 -> (32,128,112,112)
// HBM-bound streaming: 822MB read + 206MB write (mandatory, zero reuse).
//
// R8: 256-bit vector loads/stores (sm_100+ LDG.E.256 / STG.E.256).
// Each thread: 8 output pixels = one v8.f32 store (32B); reads 2x 32B from
// each of two input rows (4 front-batched 256-bit loads, 128B read/thread).
// Halves L1tex wavefront count vs float4 version at identical traffic.

#define IW   224
#define IH   224
#define OW   112
#define OH   112
#define OW8  14                       // v8 groups per output row (112/8)
#define NC   (32 * 128)
#define TOTAL_V8 (NC * OH * OW8)      // 6,422,528 = 256 * 25088

__device__ __forceinline__ void ld256cs(const float* p, float r[8]) {
    asm volatile("ld.global.cs.v8.f32 {%0,%1,%2,%3,%4,%5,%6,%7}, [%8];"
                 : "=f"(r[0]), "=f"(r[1]), "=f"(r[2]), "=f"(r[3]),
                   "=f"(r[4]), "=f"(r[5]), "=f"(r[6]), "=f"(r[7])
                 : "l"(p));
}

__device__ __forceinline__ void st256cs(float* p, const float r[8]) {
    asm volatile("st.global.cs.v8.f32 [%0], {%1,%2,%3,%4,%5,%6,%7,%8};"
                 :: "l"(p),
                    "f"(r[0]), "f"(r[1]), "f"(r[2]), "f"(r[3]),
                    "f"(r[4]), "f"(r[5]), "f"(r[6]), "f"(r[7])
                 : "memory");
}

__global__ __launch_bounds__(256, 8)
void pool2d_kernel(const float* __restrict__ in, float* __restrict__ out) {
    const int p = blockIdx.x * 256 + threadIdx.x;   // v8-output index

    const int ow8 = p % OW8;
    const int t1  = p / OW8;
    const int oh  = t1 % OH;
    const int nc  = t1 / OH;

    const long long base = (long long)nc * (IH * IW) + (long long)(2 * oh) * IW + 16 * ow8;
    const float* r0p = in + base;
    const float* r1p = r0p + IW;

    // 4 front-batched 256-bit loads
    float a0[8], a1[8], b0[8], b1[8];
    ld256cs(r0p,     a0);
    ld256cs(r0p + 8, a1);
    ld256cs(r1p,     b0);
    ld256cs(r1p + 8, b1);

    float r[8];
#pragma unroll
    for (int j = 0; j < 4; j++) {
        r[j]     = fmaxf(fmaxf(a0[2*j], a0[2*j+1]), fmaxf(b0[2*j], b0[2*j+1]));
        r[j + 4] = fmaxf(fmaxf(a1[2*j], a1[2*j+1]), fmaxf(b1[2*j], b1[2*j+1]));
    }

    st256cs(out + (long long)p * 8, r);
}

extern "C" void kernel_launch(void* const* d_in, const int* in_sizes, int n_in,
                              void* d_out, int out_size) {
    const float* x = (const float*)d_in[0];
    float* out = (float*)d_out;

    const int blocks  = TOTAL_V8 / 256;   // 25088, no tail
    const int threads = 256;

    pool2d_kernel<<<blocks, threads>>>(x, out);
}